// round 10
// baseline (speedup 1.0000x reference)
#include <cuda_runtime.h>
#include <cuda_bf16.h>
#include <cstdint>

// ---------------------------------------------------------------------------
// NONLocalBlock2D: B=2, C=64, Ci=16, H=W=80, N=6400
// Round 9: HMMA flash attention (R8) + fast proj (4-way split, channel-pair
// threads) + cp.async double-buffered attn tiles.
// ---------------------------------------------------------------------------

#define Bb 2
#define Cc 64
#define CI 16
#define NN 6400
#define KSPLIT 3
#define LOG2E 1.4426950408889634f

#define PHI_PITCH 48     // bytes/row (12 floats): conflict-free
#define G_PITCH   304    // bytes/row (76 floats): 76 mod 32 = 12 -> conflict-free
#define PHI_BYTES (128 * PHI_PITCH)   // 6144
#define G_BYTES   (32 * G_PITCH)      // 9728
#define STAGE_BYTES (PHI_BYTES + G_BYTES)  // 15872

__device__ __forceinline__ float ex2_approx(float v) {
    float r;
    asm("ex2.approx.f32 %0, %1;" : "=f"(r) : "f"(v));
    return r;
}
__device__ __forceinline__ uint32_t pack_bf16(float lo, float hi) {
    uint32_t r;
    asm("cvt.rn.bf16x2.f32 %0, %1, %2;" : "=r"(r) : "f"(hi), "f"(lo));
    return r;
}
__device__ __forceinline__ void mma16816(float c[4], const uint32_t a[4],
                                         uint32_t b0, uint32_t b1) {
    asm volatile(
        "mma.sync.aligned.m16n8k16.row.col.f32.bf16.bf16.f32 "
        "{%0,%1,%2,%3}, {%4,%5,%6,%7}, {%8,%9}, {%0,%1,%2,%3};"
        : "+f"(c[0]), "+f"(c[1]), "+f"(c[2]), "+f"(c[3])
        : "r"(a[0]), "r"(a[1]), "r"(a[2]), "r"(a[3]), "r"(b0), "r"(b1));
}
__device__ __forceinline__ uint32_t smem_u32(const void* p) {
    uint32_t a;
    asm("{ .reg .u64 t; cvta.to.shared.u64 t, %1; cvt.u32.u64 %0, t; }"
        : "=r"(a) : "l"(p));
    return a;
}
#define CP_ASYNC16(dst, src) \
    asm volatile("cp.async.ca.shared.global [%0], [%1], 16;" :: "r"(dst), "l"(src))
#define CP_COMMIT() asm volatile("cp.async.commit_group;" ::: "memory")
#define CP_WAIT(n)  asm volatile("cp.async.wait_group %0;" :: "n"(n) : "memory")

// Scratch (static device globals: no runtime allocation)
__device__ __align__(256) unsigned int   d_thetab[Bb * NN * 8];   // bf16x2, log2e folded
__device__ __align__(256) unsigned int   d_phib  [Bb * NN * 8];   // bf16x2
__device__ __align__(256) __nv_bfloat16  d_gvt   [Bb * 32 * NN];  // [b][ch][n]; 0:16 g_x, 16:32 g_bf
__device__ __align__(256) float          d_part  [KSPLIT * Bb * NN * 36];

// ---------------------------------------------------------------------------
// Kernel 1: projections. gridDim.z = 4 (theta, phi, g_bf, g_x).
// 2 threads per pixel (channel halves), merged via shfl.
// ---------------------------------------------------------------------------
__global__ __launch_bounds__(256) void proj_kernel(
    const float* __restrict__ bfimg, const float* __restrict__ x,
    const float* __restrict__ w_theta, const float* __restrict__ b_theta,
    const float* __restrict__ w_phi,   const float* __restrict__ b_phi,
    const float* __restrict__ w_g,     const float* __restrict__ b_g,
    const float* __restrict__ w_gbf,   const float* __restrict__ b_gbf)
{
    __shared__ float sw[CI * Cc];
    __shared__ float sb[CI];

    int tid = threadIdx.x;
    int z = blockIdx.z;   // 0:theta 1:phi 2:g_bf 3:g_x

    const float* W  = (z == 0) ? w_theta : (z == 1) ? w_phi : (z == 2) ? w_gbf : w_g;
    const float* Bv = (z == 0) ? b_theta : (z == 1) ? b_phi : (z == 2) ? b_gbf : b_g;
    const float* src = (z == 3) ? x : bfimg;

    for (int i = tid; i < CI * Cc; i += 256) sw[i] = W[i];
    if (tid < CI) sb[tid] = Bv[tid];
    __syncthreads();

    int pix = blockIdx.x * 128 + (tid >> 1);   // 0 .. 12799
    int half = tid & 1;
    int b = pix / NN;
    int n = pix - b * NN;

    const float* in = src + ((size_t)(b * Cc + half * 32)) * NN + n;
    float v[32];
    #pragma unroll
    for (int c = 0; c < 32; c++) v[c] = in[(size_t)c * NN];

    float outv[CI];
    #pragma unroll
    for (int ci = 0; ci < CI; ci++) {
        const float* wr = &sw[ci * Cc + half * 32];
        float a0 = half ? 0.f : sb[ci];
        float a1 = 0.f;
        #pragma unroll
        for (int c = 0; c < 32; c += 2) {
            a0 = fmaf(wr[c], v[c], a0);
            a1 = fmaf(wr[c + 1], v[c + 1], a1);
        }
        float a = a0 + a1;
        a += __shfl_xor_sync(0xFFFFFFFFu, a, 1);
        outv[ci] = a;
    }

    if (z <= 1) {
        // pack 8 values (this lane's half of 16) -> uint4
        float s = (z == 0) ? LOG2E : 1.f;
        uint32_t p0 = pack_bf16(outv[half * 8 + 0] * s, outv[half * 8 + 1] * s);
        uint32_t p1 = pack_bf16(outv[half * 8 + 2] * s, outv[half * 8 + 3] * s);
        uint32_t p2 = pack_bf16(outv[half * 8 + 4] * s, outv[half * 8 + 5] * s);
        uint32_t p3 = pack_bf16(outv[half * 8 + 6] * s, outv[half * 8 + 7] * s);
        unsigned int* dst = (z == 0) ? d_thetab : d_phib;
        *(uint4*)&dst[(size_t)pix * 8 + half * 4] = make_uint4(p0, p1, p2, p3);
    } else {
        int ch0 = (z == 2) ? 16 : 0;
        #pragma unroll
        for (int j = 0; j < 8; j++) {
            int ci = half * 8 + j;
            d_gvt[(size_t)(b * 32 + ch0 + ci) * NN + n] = __float2bfloat16(outv[ci]);
        }
    }
}

// ---------------------------------------------------------------------------
// Kernel 2: HMMA flash attention, cp.async double-buffered.
// Grid (NN/64=100, Bb, KSPLIT) = 600 CTAs, 128 threads = 4 warps x 16 queries.
// ---------------------------------------------------------------------------
__global__ __launch_bounds__(128) void attn_kernel()
{
    __shared__ __align__(16) char s_tiles[2 * STAGE_BYTES];

    int tid = threadIdx.x;
    int wid = tid >> 5, lane = tid & 31;
    int g = lane >> 2, t = lane & 3;
    int b = blockIdx.y, split = blockIdx.z;
    int qbase = blockIdx.x * 64;
    int kstart = split * 2176;
    int ntiles = (split < 2) ? 17 : 16;

    uint32_t sbase = smem_u32(s_tiles);

    int q0 = qbase + wid * 16 + g;

    // theta A-fragment (constant)
    uint32_t a_th[4];
    {
        const unsigned int* th0 = d_thetab + ((size_t)b * NN + q0) * 8;
        const unsigned int* th1 = th0 + 8 * 8;       // q0 + 8
        a_th[0] = th0[t];     a_th[1] = th1[t];
        a_th[2] = th0[t + 4]; a_th[3] = th1[t + 4];
    }

    float o[4][4];
    #pragma unroll
    for (int nb = 0; nb < 4; nb++)
        #pragma unroll
        for (int i = 0; i < 4; i++) o[nb][i] = 0.f;
    float sumA = 0.f, sumB = 0.f;

    // tile loader: phi (2x16B) + g (4x16B) per thread via cp.async
    auto load_tile = [&](int stage, int kbase) {
        uint32_t ph = sbase + stage * STAGE_BYTES;
        uint32_t gb = ph + PHI_BYTES;
        const float4* psrc = (const float4*)(d_phib + ((size_t)b * NN + kbase) * 8);
        #pragma unroll
        for (int i = tid; i < 256; i += 128) {
            int key = i >> 1, h = i & 1;
            CP_ASYNC16(ph + key * PHI_PITCH + h * 16, psrc + i);
        }
        #pragma unroll
        for (int i = tid; i < 512; i += 128) {
            int ch = i >> 4, seg = i & 15;
            const void* src = d_gvt + (size_t)(b * 32 + ch) * NN + kbase + seg * 8;
            CP_ASYNC16(gb + ch * G_PITCH + seg * 16, src);
        }
    };

    load_tile(0, kstart);
    CP_COMMIT();

    for (int tt = 0; tt < ntiles; tt++) {
        if (tt + 1 < ntiles) {
            load_tile((tt + 1) & 1, kstart + (tt + 1) * 128);
            CP_COMMIT();
            CP_WAIT(1);
        } else {
            CP_WAIT(0);
        }
        __syncthreads();

        const char* s_phi = s_tiles + (tt & 1) * STAGE_BYTES;
        const char* s_g = s_phi + PHI_BYTES;

        #pragma unroll 2
        for (int kk = 0; kk < 8; kk++) {
            float s0[4] = {0.f, 0.f, 0.f, 0.f};
            float s1[4] = {0.f, 0.f, 0.f, 0.f};
            {
                const char* r0 = s_phi + (16 * kk + g) * PHI_PITCH + 4 * t;
                mma16816(s0, a_th, *(const uint32_t*)r0, *(const uint32_t*)(r0 + 16));
                const char* r1 = r0 + 8 * PHI_PITCH;
                mma16816(s1, a_th, *(const uint32_t*)r1, *(const uint32_t*)(r1 + 16));
            }
            #pragma unroll
            for (int i = 0; i < 4; i++) {
                s0[i] = ex2_approx(s0[i]);
                s1[i] = ex2_approx(s1[i]);
            }
            sumA += (s0[0] + s0[1]) + (s1[0] + s1[1]);
            sumB += (s0[2] + s0[3]) + (s1[2] + s1[3]);
            uint32_t a_p[4];
            a_p[0] = pack_bf16(s0[0], s0[1]);
            a_p[1] = pack_bf16(s0[2], s0[3]);
            a_p[2] = pack_bf16(s1[0], s1[1]);
            a_p[3] = pack_bf16(s1[2], s1[3]);
            const char* gb = s_g + g * G_PITCH + 32 * kk + 4 * t;
            #pragma unroll
            for (int nb = 0; nb < 4; nb++) {
                const char* r = gb + nb * 8 * G_PITCH;
                mma16816(o[nb], a_p, *(const uint32_t*)r, *(const uint32_t*)(r + 16));
            }
        }
        __syncthreads();   // release this stage before it is refilled
    }

    sumA += __shfl_xor_sync(0xFFFFFFFFu, sumA, 1);
    sumA += __shfl_xor_sync(0xFFFFFFFFu, sumA, 2);
    sumB += __shfl_xor_sync(0xFFFFFFFFu, sumB, 1);
    sumB += __shfl_xor_sync(0xFFFFFFFFu, sumB, 2);

    {
        size_t base0 = (((size_t)split * Bb + b) * NN + q0) * 36;
        size_t base1 = base0 + 8 * 36;       // q0 + 8
        #pragma unroll
        for (int nb = 0; nb < 4; nb++) {
            int ch = 8 * nb + 2 * t;
            *(float2*)(d_part + base0 + ch) = make_float2(o[nb][0], o[nb][1]);
            *(float2*)(d_part + base1 + ch) = make_float2(o[nb][2], o[nb][3]);
        }
        if (t == 0) {
            d_part[base0 + 32] = sumA;
            d_part[base1 + 32] = sumB;
        }
    }
}

// ---------------------------------------------------------------------------
// Kernel 3: combine splits, normalize, W/BN/residual epilogue. fp32.
// ---------------------------------------------------------------------------
__global__ __launch_bounds__(256) void combine_kernel(
    const float* __restrict__ bfimg, const float* __restrict__ x,
    const float* __restrict__ w_W,   const float* __restrict__ b_W,
    const float* __restrict__ bn_gamma, const float* __restrict__ bn_beta,
    const float* __restrict__ bn_mean,  const float* __restrict__ bn_var,
    float* __restrict__ out)
{
    __shared__ float s_w[Cc * CI];
    __shared__ float s_scale[Cc];
    __shared__ float s_bias[Cc];
    __shared__ float s_y[64][36];

    int tid = threadIdx.x;
    int b = blockIdx.y;
    int q_local = tid >> 2;
    int tsub = tid & 3;
    int q = blockIdx.x * 64 + q_local;

    for (int i = tid; i < Cc * CI; i += 256) s_w[i] = w_W[i];
    if (tid < Cc) {
        float sc = bn_gamma[tid] * rsqrtf(bn_var[tid] + 1e-5f);
        s_scale[tid] = sc;
        s_bias[tid] = (b_W[tid] - bn_mean[tid]) * sc + bn_beta[tid];
    }

    float y0 = 0.f, y1v = 0.f, y2v = 0.f, y3 = 0.f, y4 = 0.f, y5 = 0.f, y6 = 0.f, y7 = 0.f;
    float sp = 0.f;
    #pragma unroll
    for (int s = 0; s < KSPLIT; s++) {
        const float* p = d_part + (((size_t)s * Bb + b) * NN + q) * 36;
        float4 v0 = *(const float4*)(p + tsub * 8);
        float4 v1 = *(const float4*)(p + tsub * 8 + 4);
        y0 += v0.x; y1v += v0.y; y2v += v0.z; y3 += v0.w;
        y4 += v1.x; y5 += v1.y; y6 += v1.z; y7 += v1.w;
        sp += p[32];
    }
    float inv = 1.f / sp;
    int cb = tsub * 8;
    s_y[q_local][cb + 0] = y0 * inv;  s_y[q_local][cb + 1] = y1v * inv;
    s_y[q_local][cb + 2] = y2v * inv; s_y[q_local][cb + 3] = y3 * inv;
    s_y[q_local][cb + 4] = y4 * inv;  s_y[q_local][cb + 5] = y5 * inv;
    s_y[q_local][cb + 6] = y6 * inv;  s_y[q_local][cb + 7] = y7 * inv;
    __syncthreads();

    float ya[16], yb[16];
    #pragma unroll
    for (int i = 0; i < 16; i++) { ya[i] = s_y[q_local][i]; yb[i] = s_y[q_local][16 + i]; }

    int n = q;
    #pragma unroll 1
    for (int cc = 0; cc < 16; cc++) {
        int c = tsub * 16 + cc;
        float d1 = 0.f, d2 = 0.f;
        #pragma unroll
        for (int i = 0; i < 16; i++) {
            float w = s_w[c * CI + i];
            d1 = fmaf(w, ya[i], d1);
            d2 = fmaf(w, yb[i], d2);
        }
        float sc = s_scale[c], bi = s_bias[c];
        out[((size_t)(b * 128) + c) * NN + n] =
            fmaf(sc, d1, bi) + x[((size_t)(b * Cc) + c) * NN + n];
        out[((size_t)(b * 128) + 64 + c) * NN + n] =
            fmaf(sc, d2, bi) + bfimg[((size_t)(b * Cc) + c) * NN + n];
    }
}

// ---------------------------------------------------------------------------
extern "C" void kernel_launch(void* const* d_in, const int* in_sizes, int n_in,
                              void* d_out, int out_size)
{
    const float* bfimg   = (const float*)d_in[0];
    const float* x       = (const float*)d_in[1];
    const float* w_theta = (const float*)d_in[2];
    const float* b_theta = (const float*)d_in[3];
    const float* w_phi   = (const float*)d_in[4];
    const float* b_phi   = (const float*)d_in[5];
    const float* w_g     = (const float*)d_in[6];
    const float* b_g     = (const float*)d_in[7];
    const float* w_gbf   = (const float*)d_in[8];
    const float* b_gbf   = (const float*)d_in[9];
    const float* w_W     = (const float*)d_in[10];
    const float* b_W     = (const float*)d_in[11];
    const float* bn_gamma= (const float*)d_in[12];
    const float* bn_beta = (const float*)d_in[13];
    const float* bn_mean = (const float*)d_in[14];
    const float* bn_var  = (const float*)d_in[15];
    float* out = (float*)d_out;

    proj_kernel<<<dim3((Bb * NN) / 128, 1, 4), 256>>>(bfimg, x, w_theta, b_theta,
                                                      w_phi, b_phi, w_g, b_g,
                                                      w_gbf, b_gbf);
    attn_kernel<<<dim3(NN / 64, Bb, KSPLIT), 128>>>();
    combine_kernel<<<dim3(NN / 64, Bb), 256>>>(bfimg, x, w_W, b_W,
                                               bn_gamma, bn_beta, bn_mean, bn_var, out);
}

// round 11
// speedup vs baseline: 1.4373x; 1.4373x over previous
#include <cuda_runtime.h>
#include <cuda_bf16.h>
#include <cstdint>

// ---------------------------------------------------------------------------
// NONLocalBlock2D: B=2, C=64, Ci=16, H=W=80, N=6400
// Round 10: R8 HMMA flash attention (verbatim) + proj split by OUTPUT tensor
// (gridDim.z=4), keeping the coalesced one-thread-per-pixel access pattern.
// ---------------------------------------------------------------------------

#define Bb 2
#define Cc 64
#define CI 16
#define NN 6400
#define KSPLIT 3
#define LOG2E 1.4426950408889634f

#define PHI_PITCH 48     // bytes/row (12 floats): conflict-free
#define G_PITCH   304    // bytes/row (76 floats): 76 mod 32 = 12 -> conflict-free

__device__ __forceinline__ float ex2_approx(float v) {
    float r;
    asm("ex2.approx.f32 %0, %1;" : "=f"(r) : "f"(v));
    return r;
}
__device__ __forceinline__ uint32_t pack_bf16(float lo, float hi) {
    uint32_t r;
    asm("cvt.rn.bf16x2.f32 %0, %1, %2;" : "=r"(r) : "f"(hi), "f"(lo));
    return r;
}
__device__ __forceinline__ void mma16816(float c[4], const uint32_t a[4],
                                         uint32_t b0, uint32_t b1) {
    asm volatile(
        "mma.sync.aligned.m16n8k16.row.col.f32.bf16.bf16.f32 "
        "{%0,%1,%2,%3}, {%4,%5,%6,%7}, {%8,%9}, {%0,%1,%2,%3};"
        : "+f"(c[0]), "+f"(c[1]), "+f"(c[2]), "+f"(c[3])
        : "r"(a[0]), "r"(a[1]), "r"(a[2]), "r"(a[3]), "r"(b0), "r"(b1));
}

// Scratch (static device globals: no runtime allocation)
__device__ __align__(256) unsigned int   d_thetab[Bb * NN * 8];   // bf16x2, log2e folded
__device__ __align__(256) unsigned int   d_phib  [Bb * NN * 8];   // bf16x2
__device__ __align__(256) __nv_bfloat16  d_gvt   [Bb * 32 * NN];  // [b][ch][n]; 0:16 g_x, 16:32 g_bf
__device__ __align__(256) float          d_part  [KSPLIT * Bb * NN * 36];

// ---------------------------------------------------------------------------
// Kernel 1: projections. gridDim.z = 4 (0:theta 1:phi 2:g_bf 3:g_x).
// One thread per pixel (fully coalesced input loads), 16 independent
// accumulator chains per thread.
// ---------------------------------------------------------------------------
__global__ __launch_bounds__(256) void proj_kernel(
    const float* __restrict__ bfimg, const float* __restrict__ x,
    const float* __restrict__ w_theta, const float* __restrict__ b_theta,
    const float* __restrict__ w_phi,   const float* __restrict__ b_phi,
    const float* __restrict__ w_g,     const float* __restrict__ b_g,
    const float* __restrict__ w_gbf,   const float* __restrict__ b_gbf)
{
    __shared__ float sw[CI * Cc];
    __shared__ float sb[CI];

    int tid = threadIdx.x;
    int z = blockIdx.z;

    const float* W  = (z == 0) ? w_theta : (z == 1) ? w_phi : (z == 2) ? w_gbf : w_g;
    const float* Bv = (z == 0) ? b_theta : (z == 1) ? b_phi : (z == 2) ? b_gbf : b_g;
    const float* src = (z == 3) ? x : bfimg;

    for (int i = tid; i < CI * Cc; i += 256) sw[i] = W[i];
    if (tid < CI) sb[tid] = Bv[tid];
    __syncthreads();

    int pix = blockIdx.x * 256 + tid;          // 0 .. 12799
    int b = pix / NN;
    int n = pix - b * NN;

    const float* in = src + (size_t)(b * Cc) * NN + n;
    float v[Cc];
    #pragma unroll
    for (int c = 0; c < Cc; c++) v[c] = in[(size_t)c * NN];

    float outv[CI];
    #pragma unroll
    for (int ci = 0; ci < CI; ci++) {
        const float* wr = &sw[ci * Cc];
        float a0 = sb[ci], a1 = 0.f, a2 = 0.f, a3 = 0.f;
        #pragma unroll
        for (int c = 0; c < Cc; c += 4) {
            a0 = fmaf(wr[c],     v[c],     a0);
            a1 = fmaf(wr[c + 1], v[c + 1], a1);
            a2 = fmaf(wr[c + 2], v[c + 2], a2);
            a3 = fmaf(wr[c + 3], v[c + 3], a3);
        }
        outv[ci] = (a0 + a1) + (a2 + a3);
    }

    if (z <= 1) {
        float s = (z == 0) ? LOG2E : 1.f;
        unsigned int pk[8];
        #pragma unroll
        for (int j = 0; j < 8; j++)
            pk[j] = pack_bf16(outv[2 * j] * s, outv[2 * j + 1] * s);
        unsigned int* dst = (z == 0) ? d_thetab : d_phib;
        *(uint4*)&dst[(size_t)pix * 8]     = make_uint4(pk[0], pk[1], pk[2], pk[3]);
        *(uint4*)&dst[(size_t)pix * 8 + 4] = make_uint4(pk[4], pk[5], pk[6], pk[7]);
    } else {
        int ch0 = (z == 2) ? 16 : 0;
        #pragma unroll
        for (int ci = 0; ci < CI; ci++)
            d_gvt[(size_t)(b * 32 + ch0 + ci) * NN + n] = __float2bfloat16(outv[ci]);
    }
}

// ---------------------------------------------------------------------------
// Kernel 2: HMMA flash attention (R8 verbatim). Grid (NN/64=100, Bb, KSPLIT)
// = 600 CTAs, 128 threads = 4 warps x 16 queries. Splits: 17/17/16 tiles.
// ---------------------------------------------------------------------------
__global__ __launch_bounds__(128) void attn_kernel()
{
    __shared__ __align__(16) char s_phi[128 * PHI_PITCH];  // 6144 B
    __shared__ __align__(16) char s_g[32 * G_PITCH];       // 9728 B

    int tid = threadIdx.x;
    int wid = tid >> 5, lane = tid & 31;
    int g = lane >> 2, t = lane & 3;
    int b = blockIdx.y, split = blockIdx.z;
    int qbase = blockIdx.x * 64;
    int kstart = split * 2176;
    int ntiles = (split < 2) ? 17 : 16;

    int q0 = qbase + wid * 16 + g;             // rows g and g+8 of this warp's M=16

    // theta A-fragment (constant for whole kernel)
    uint32_t a_th[4];
    {
        const unsigned int* th0 = d_thetab + ((size_t)b * NN + q0) * 8;
        const unsigned int* th1 = th0 + 8 * 8;       // q0 + 8
        a_th[0] = th0[t];     a_th[1] = th1[t];
        a_th[2] = th0[t + 4]; a_th[3] = th1[t + 4];
    }

    float o[4][4];
    #pragma unroll
    for (int nb = 0; nb < 4; nb++)
        #pragma unroll
        for (int i = 0; i < 4; i++) o[nb][i] = 0.f;
    float sumA = 0.f, sumB = 0.f;

    for (int tt = 0; tt < ntiles; tt++) {
        int kbase = kstart + tt * 128;
        __syncthreads();
        // phi tile: 128 keys x 32B -> rows of PHI_PITCH
        {
            const float4* src = (const float4*)(d_phib + ((size_t)b * NN + kbase) * 8);
            #pragma unroll
            for (int i = tid; i < 256; i += 128) {
                int key = i >> 1, h = i & 1;
                *(float4*)(s_phi + key * PHI_PITCH + h * 16) = src[i];
            }
        }
        // g tile: 32 ch x 128 keys (256B) -> rows of G_PITCH
        {
            #pragma unroll
            for (int i = tid; i < 512; i += 128) {
                int ch = i >> 4, seg = i & 15;
                const float4* src = (const float4*)(d_gvt + (size_t)(b * 32 + ch) * NN + kbase + seg * 8);
                *(float4*)(s_g + ch * G_PITCH + seg * 16) = src[0];
            }
        }
        __syncthreads();

        #pragma unroll 2
        for (int kk = 0; kk < 8; kk++) {
            // MMA1: two S tiles (keys 16kk .. 16kk+15)
            float s0[4] = {0.f, 0.f, 0.f, 0.f};
            float s1[4] = {0.f, 0.f, 0.f, 0.f};
            {
                const char* r0 = s_phi + (16 * kk + g) * PHI_PITCH + 4 * t;
                mma16816(s0, a_th, *(const uint32_t*)r0, *(const uint32_t*)(r0 + 16));
                const char* r1 = r0 + 8 * PHI_PITCH;
                mma16816(s1, a_th, *(const uint32_t*)r1, *(const uint32_t*)(r1 + 16));
            }
            // exp (ex2; theta pre-scaled by log2e)
            #pragma unroll
            for (int i = 0; i < 4; i++) {
                s0[i] = ex2_approx(s0[i]);
                s1[i] = ex2_approx(s1[i]);
            }
            sumA += (s0[0] + s0[1]) + (s1[0] + s1[1]);
            sumB += (s0[2] + s0[3]) + (s1[2] + s1[3]);
            // C-frag -> A-frag repack (P, K=16 keys)
            uint32_t a_p[4];
            a_p[0] = pack_bf16(s0[0], s0[1]);
            a_p[1] = pack_bf16(s0[2], s0[3]);
            a_p[2] = pack_bf16(s1[0], s1[1]);
            a_p[3] = pack_bf16(s1[2], s1[3]);
            // MMA2: O += P @ g^T over 4 channel blocks
            const char* gb = s_g + g * G_PITCH + 32 * kk + 4 * t;
            #pragma unroll
            for (int nb = 0; nb < 4; nb++) {
                const char* r = gb + nb * 8 * G_PITCH;
                mma16816(o[nb], a_p, *(const uint32_t*)r, *(const uint32_t*)(r + 16));
            }
        }
    }

    // row sums: reduce over the quad (t)
    sumA += __shfl_xor_sync(0xFFFFFFFFu, sumA, 1);
    sumA += __shfl_xor_sync(0xFFFFFFFFu, sumA, 2);
    sumB += __shfl_xor_sync(0xFFFFFFFFu, sumB, 1);
    sumB += __shfl_xor_sync(0xFFFFFFFFu, sumB, 2);

    // write unnormalized partials
    {
        size_t base0 = (((size_t)split * Bb + b) * NN + q0) * 36;
        size_t base1 = base0 + 8 * 36;       // q0 + 8
        #pragma unroll
        for (int nb = 0; nb < 4; nb++) {
            int ch = 8 * nb + 2 * t;
            *(float2*)(d_part + base0 + ch) = make_float2(o[nb][0], o[nb][1]);
            *(float2*)(d_part + base1 + ch) = make_float2(o[nb][2], o[nb][3]);
        }
        if (t == 0) {
            d_part[base0 + 32] = sumA;
            d_part[base1 + 32] = sumB;
        }
    }
}

// ---------------------------------------------------------------------------
// Kernel 3: combine splits, normalize, W/BN/residual epilogue. fp32.
// ---------------------------------------------------------------------------
__global__ __launch_bounds__(256) void combine_kernel(
    const float* __restrict__ bfimg, const float* __restrict__ x,
    const float* __restrict__ w_W,   const float* __restrict__ b_W,
    const float* __restrict__ bn_gamma, const float* __restrict__ bn_beta,
    const float* __restrict__ bn_mean,  const float* __restrict__ bn_var,
    float* __restrict__ out)
{
    __shared__ float s_w[Cc * CI];
    __shared__ float s_scale[Cc];
    __shared__ float s_bias[Cc];
    __shared__ float s_y[64][36];

    int tid = threadIdx.x;
    int b = blockIdx.y;
    int q_local = tid >> 2;
    int tsub = tid & 3;
    int q = blockIdx.x * 64 + q_local;

    for (int i = tid; i < Cc * CI; i += 256) s_w[i] = w_W[i];
    if (tid < Cc) {
        float sc = bn_gamma[tid] * rsqrtf(bn_var[tid] + 1e-5f);
        s_scale[tid] = sc;
        s_bias[tid] = (b_W[tid] - bn_mean[tid]) * sc + bn_beta[tid];
    }

    float y0 = 0.f, y1v = 0.f, y2v = 0.f, y3 = 0.f, y4 = 0.f, y5 = 0.f, y6 = 0.f, y7 = 0.f;
    float sp = 0.f;
    #pragma unroll
    for (int s = 0; s < KSPLIT; s++) {
        const float* p = d_part + (((size_t)s * Bb + b) * NN + q) * 36;
        float4 v0 = *(const float4*)(p + tsub * 8);
        float4 v1 = *(const float4*)(p + tsub * 8 + 4);
        y0 += v0.x; y1v += v0.y; y2v += v0.z; y3 += v0.w;
        y4 += v1.x; y5 += v1.y; y6 += v1.z; y7 += v1.w;
        sp += p[32];
    }
    float inv = 1.f / sp;
    int cb = tsub * 8;
    s_y[q_local][cb + 0] = y0 * inv;  s_y[q_local][cb + 1] = y1v * inv;
    s_y[q_local][cb + 2] = y2v * inv; s_y[q_local][cb + 3] = y3 * inv;
    s_y[q_local][cb + 4] = y4 * inv;  s_y[q_local][cb + 5] = y5 * inv;
    s_y[q_local][cb + 6] = y6 * inv;  s_y[q_local][cb + 7] = y7 * inv;
    __syncthreads();

    float ya[16], yb[16];
    #pragma unroll
    for (int i = 0; i < 16; i++) { ya[i] = s_y[q_local][i]; yb[i] = s_y[q_local][16 + i]; }

    int n = q;
    #pragma unroll 1
    for (int cc = 0; cc < 16; cc++) {
        int c = tsub * 16 + cc;
        float d1 = 0.f, d2 = 0.f;
        #pragma unroll
        for (int i = 0; i < 16; i++) {
            float w = s_w[c * CI + i];
            d1 = fmaf(w, ya[i], d1);
            d2 = fmaf(w, yb[i], d2);
        }
        float sc = s_scale[c], bi = s_bias[c];
        out[((size_t)(b * 128) + c) * NN + n] =
            fmaf(sc, d1, bi) + x[((size_t)(b * Cc) + c) * NN + n];
        out[((size_t)(b * 128) + 64 + c) * NN + n] =
            fmaf(sc, d2, bi) + bfimg[((size_t)(b * Cc) + c) * NN + n];
    }
}

// ---------------------------------------------------------------------------
extern "C" void kernel_launch(void* const* d_in, const int* in_sizes, int n_in,
                              void* d_out, int out_size)
{
    const float* bfimg   = (const float*)d_in[0];
    const float* x       = (const float*)d_in[1];
    const float* w_theta = (const float*)d_in[2];
    const float* b_theta = (const float*)d_in[3];
    const float* w_phi   = (const float*)d_in[4];
    const float* b_phi   = (const float*)d_in[5];
    const float* w_g     = (const float*)d_in[6];
    const float* b_g     = (const float*)d_in[7];
    const float* w_gbf   = (const float*)d_in[8];
    const float* b_gbf   = (const float*)d_in[9];
    const float* w_W     = (const float*)d_in[10];
    const float* b_W     = (const float*)d_in[11];
    const float* bn_gamma= (const float*)d_in[12];
    const float* bn_beta = (const float*)d_in[13];
    const float* bn_mean = (const float*)d_in[14];
    const float* bn_var  = (const float*)d_in[15];
    float* out = (float*)d_out;

    proj_kernel<<<dim3((Bb * NN) / 256, 1, 4), 256>>>(bfimg, x, w_theta, b_theta,
                                                      w_phi, b_phi, w_g, b_g,
                                                      w_gbf, b_gbf);
    attn_kernel<<<dim3(NN / 64, Bb, KSPLIT), 128>>>();
    combine_kernel<<<dim3(NN / 64, Bb), 256>>>(bfimg, x, w_W, b_W,
                                               bn_gamma, bn_beta, bn_mean, bn_var, out);
}

// round 14
// speedup vs baseline: 1.5043x; 1.0466x over previous
#include <cuda_runtime.h>
#include <cuda_bf16.h>
#include <cstdint>

// ---------------------------------------------------------------------------
// NONLocalBlock2D: B=2, C=64, Ci=16, H=W=80, N=6400
// Round 11: R10 HMMA flash attention with KSPLIT=5 (1000 CTAs -> ~7 CTAs/SM)
// + chunked-accumulator proj (low regs, 128-thr blocks -> 400 CTAs).
// ---------------------------------------------------------------------------

#define Bb 2
#define Cc 64
#define CI 16
#define NN 6400
#define KSPLIT 5
#define LOG2E 1.4426950408889634f

#define PHI_PITCH 48     // bytes/row (12 floats): conflict-free
#define G_PITCH   304    // bytes/row (76 floats): 76 mod 32 = 12 -> conflict-free

__device__ __forceinline__ float ex2_approx(float v) {
    float r;
    asm("ex2.approx.f32 %0, %1;" : "=f"(r) : "f"(v));
    return r;
}
__device__ __forceinline__ uint32_t pack_bf16(float lo, float hi) {
    uint32_t r;
    asm("cvt.rn.bf16x2.f32 %0, %1, %2;" : "=r"(r) : "f"(hi), "f"(lo));
    return r;
}
__device__ __forceinline__ void mma16816(float c[4], const uint32_t a[4],
                                         uint32_t b0, uint32_t b1) {
    asm volatile(
        "mma.sync.aligned.m16n8k16.row.col.f32.bf16.bf16.f32 "
        "{%0,%1,%2,%3}, {%4,%5,%6,%7}, {%8,%9}, {%0,%1,%2,%3};"
        : "+f"(c[0]), "+f"(c[1]), "+f"(c[2]), "+f"(c[3])
        : "r"(a[0]), "r"(a[1]), "r"(a[2]), "r"(a[3]), "r"(b0), "r"(b1));
}

// Scratch (static device globals: no runtime allocation)
__device__ __align__(256) unsigned int   d_thetab[Bb * NN * 8];   // bf16x2, log2e folded
__device__ __align__(256) unsigned int   d_phib  [Bb * NN * 8];   // bf16x2
__device__ __align__(256) __nv_bfloat16  d_gvt   [Bb * 32 * NN];  // [b][ch][n]; 0:16 g_x, 16:32 g_bf
__device__ __align__(256) float          d_part  [KSPLIT * Bb * NN * 36];

// ---------------------------------------------------------------------------
// Kernel 1: projections. gridDim.z = 4 (0:theta 1:phi 2:g_bf 3:g_x).
// 128-thread blocks, one thread per pixel, chunked accumulation (4 x v[16])
// to keep registers low and residency high.
// ---------------------------------------------------------------------------
__global__ __launch_bounds__(128) void proj_kernel(
    const float* __restrict__ bfimg, const float* __restrict__ x,
    const float* __restrict__ w_theta, const float* __restrict__ b_theta,
    const float* __restrict__ w_phi,   const float* __restrict__ b_phi,
    const float* __restrict__ w_g,     const float* __restrict__ b_g,
    const float* __restrict__ w_gbf,   const float* __restrict__ b_gbf)
{
    __shared__ float sw[CI * Cc];
    __shared__ float sb[CI];

    int tid = threadIdx.x;
    int z = blockIdx.z;

    const float* W  = (z == 0) ? w_theta : (z == 1) ? w_phi : (z == 2) ? w_gbf : w_g;
    const float* Bv = (z == 0) ? b_theta : (z == 1) ? b_phi : (z == 2) ? b_gbf : b_g;
    const float* src = (z == 3) ? x : bfimg;

    for (int i = tid; i < CI * Cc; i += 128) sw[i] = W[i];
    if (tid < CI) sb[tid] = Bv[tid];
    __syncthreads();

    int pix = blockIdx.x * 128 + tid;          // 0 .. 12799
    int b = pix / NN;
    int n = pix - b * NN;

    const float* in = src + (size_t)(b * Cc) * NN + n;

    float acc[CI];
    #pragma unroll
    for (int ci = 0; ci < CI; ci++) acc[ci] = sb[ci];

    #pragma unroll
    for (int ch = 0; ch < 4; ch++) {
        float v[16];
        #pragma unroll
        for (int c = 0; c < 16; c++) v[c] = in[(size_t)(ch * 16 + c) * NN];
        #pragma unroll
        for (int ci = 0; ci < CI; ci++) {
            const float* wr = &sw[ci * Cc + ch * 16];
            float a = acc[ci];
            #pragma unroll
            for (int c = 0; c < 16; c++)
                a = fmaf(wr[c], v[c], a);
            acc[ci] = a;
        }
    }

    if (z <= 1) {
        float s = (z == 0) ? LOG2E : 1.f;
        unsigned int pk[8];
        #pragma unroll
        for (int j = 0; j < 8; j++)
            pk[j] = pack_bf16(acc[2 * j] * s, acc[2 * j + 1] * s);
        unsigned int* dst = (z == 0) ? d_thetab : d_phib;
        *(uint4*)&dst[(size_t)pix * 8]     = make_uint4(pk[0], pk[1], pk[2], pk[3]);
        *(uint4*)&dst[(size_t)pix * 8 + 4] = make_uint4(pk[4], pk[5], pk[6], pk[7]);
    } else {
        int ch0 = (z == 2) ? 16 : 0;
        #pragma unroll
        for (int ci = 0; ci < CI; ci++)
            d_gvt[(size_t)(b * 32 + ch0 + ci) * NN + n] = __float2bfloat16(acc[ci]);
    }
}

// ---------------------------------------------------------------------------
// Kernel 2: HMMA flash attention. Grid (NN/64=100, Bb, KSPLIT=5) = 1000 CTAs,
// 128 threads = 4 warps x 16 queries. 10 tiles of 128 keys per split.
// ---------------------------------------------------------------------------
__global__ __launch_bounds__(128) void attn_kernel()
{
    __shared__ __align__(16) char s_phi[128 * PHI_PITCH];  // 6144 B
    __shared__ __align__(16) char s_g[32 * G_PITCH];       // 9728 B

    int tid = threadIdx.x;
    int wid = tid >> 5, lane = tid & 31;
    int g = lane >> 2, t = lane & 3;
    int b = blockIdx.y, split = blockIdx.z;
    int qbase = blockIdx.x * 64;
    int kstart = split * (NN / KSPLIT);        // 1280 keys per split
    const int ntiles = (NN / KSPLIT) / 128;    // 10

    int q0 = qbase + wid * 16 + g;             // rows g and g+8 of this warp's M=16

    // theta A-fragment (constant for whole kernel)
    uint32_t a_th[4];
    {
        const unsigned int* th0 = d_thetab + ((size_t)b * NN + q0) * 8;
        const unsigned int* th1 = th0 + 8 * 8;       // q0 + 8
        a_th[0] = th0[t];     a_th[1] = th1[t];
        a_th[2] = th0[t + 4]; a_th[3] = th1[t + 4];
    }

    float o[4][4];
    #pragma unroll
    for (int nb = 0; nb < 4; nb++)
        #pragma unroll
        for (int i = 0; i < 4; i++) o[nb][i] = 0.f;
    float sumA = 0.f, sumB = 0.f;

    for (int tt = 0; tt < ntiles; tt++) {
        int kbase = kstart + tt * 128;
        __syncthreads();
        // phi tile: 128 keys x 32B -> rows of PHI_PITCH
        {
            const float4* src = (const float4*)(d_phib + ((size_t)b * NN + kbase) * 8);
            #pragma unroll
            for (int i = tid; i < 256; i += 128) {
                int key = i >> 1, h = i & 1;
                *(float4*)(s_phi + key * PHI_PITCH + h * 16) = src[i];
            }
        }
        // g tile: 32 ch x 128 keys (256B) -> rows of G_PITCH
        {
            #pragma unroll
            for (int i = tid; i < 512; i += 128) {
                int ch = i >> 4, seg = i & 15;
                const float4* src = (const float4*)(d_gvt + (size_t)(b * 32 + ch) * NN + kbase + seg * 8);
                *(float4*)(s_g + ch * G_PITCH + seg * 16) = src[0];
            }
        }
        __syncthreads();

        #pragma unroll 2
        for (int kk = 0; kk < 8; kk++) {
            // MMA1: two S tiles (keys 16kk .. 16kk+15)
            float s0[4] = {0.f, 0.f, 0.f, 0.f};
            float s1[4] = {0.f, 0.f, 0.f, 0.f};
            {
                const char* r0 = s_phi + (16 * kk + g) * PHI_PITCH + 4 * t;
                mma16816(s0, a_th, *(const uint32_t*)r0, *(const uint32_t*)(r0 + 16));
                const char* r1 = r0 + 8 * PHI_PITCH;
                mma16816(s1, a_th, *(const uint32_t*)r1, *(const uint32_t*)(r1 + 16));
            }
            // exp (ex2; theta pre-scaled by log2e)
            #pragma unroll
            for (int i = 0; i < 4; i++) {
                s0[i] = ex2_approx(s0[i]);
                s1[i] = ex2_approx(s1[i]);
            }
            sumA += (s0[0] + s0[1]) + (s1[0] + s1[1]);
            sumB += (s0[2] + s0[3]) + (s1[2] + s1[3]);
            // C-frag -> A-frag repack (P, K=16 keys)
            uint32_t a_p[4];
            a_p[0] = pack_bf16(s0[0], s0[1]);
            a_p[1] = pack_bf16(s0[2], s0[3]);
            a_p[2] = pack_bf16(s1[0], s1[1]);
            a_p[3] = pack_bf16(s1[2], s1[3]);
            // MMA2: O += P @ g^T over 4 channel blocks
            const char* gb = s_g + g * G_PITCH + 32 * kk + 4 * t;
            #pragma unroll
            for (int nb = 0; nb < 4; nb++) {
                const char* r = gb + nb * 8 * G_PITCH;
                mma16816(o[nb], a_p, *(const uint32_t*)r, *(const uint32_t*)(r + 16));
            }
        }
    }

    // row sums: reduce over the quad (t)
    sumA += __shfl_xor_sync(0xFFFFFFFFu, sumA, 1);
    sumA += __shfl_xor_sync(0xFFFFFFFFu, sumA, 2);
    sumB += __shfl_xor_sync(0xFFFFFFFFu, sumB, 1);
    sumB += __shfl_xor_sync(0xFFFFFFFFu, sumB, 2);

    // write unnormalized partials
    {
        size_t base0 = (((size_t)split * Bb + b) * NN + q0) * 36;
        size_t base1 = base0 + 8 * 36;       // q0 + 8
        #pragma unroll
        for (int nb = 0; nb < 4; nb++) {
            int ch = 8 * nb + 2 * t;
            *(float2*)(d_part + base0 + ch) = make_float2(o[nb][0], o[nb][1]);
            *(float2*)(d_part + base1 + ch) = make_float2(o[nb][2], o[nb][3]);
        }
        if (t == 0) {
            d_part[base0 + 32] = sumA;
            d_part[base1 + 32] = sumB;
        }
    }
}

// ---------------------------------------------------------------------------
// Kernel 3: combine splits, normalize, W/BN/residual epilogue. fp32.
// ---------------------------------------------------------------------------
__global__ __launch_bounds__(256) void combine_kernel(
    const float* __restrict__ bfimg, const float* __restrict__ x,
    const float* __restrict__ w_W,   const float* __restrict__ b_W,
    const float* __restrict__ bn_gamma, const float* __restrict__ bn_beta,
    const float* __restrict__ bn_mean,  const float* __restrict__ bn_var,
    float* __restrict__ out)
{
    __shared__ float s_w[Cc * CI];
    __shared__ float s_scale[Cc];
    __shared__ float s_bias[Cc];
    __shared__ float s_y[64][36];

    int tid = threadIdx.x;
    int b = blockIdx.y;
    int q_local = tid >> 2;
    int tsub = tid & 3;
    int q = blockIdx.x * 64 + q_local;

    for (int i = tid; i < Cc * CI; i += 256) s_w[i] = w_W[i];
    if (tid < Cc) {
        float sc = bn_gamma[tid] * rsqrtf(bn_var[tid] + 1e-5f);
        s_scale[tid] = sc;
        s_bias[tid] = (b_W[tid] - bn_mean[tid]) * sc + bn_beta[tid];
    }

    float y0 = 0.f, y1v = 0.f, y2v = 0.f, y3 = 0.f, y4 = 0.f, y5 = 0.f, y6 = 0.f, y7 = 0.f;
    float sp = 0.f;
    #pragma unroll
    for (int s = 0; s < KSPLIT; s++) {
        const float* p = d_part + (((size_t)s * Bb + b) * NN + q) * 36;
        float4 v0 = *(const float4*)(p + tsub * 8);
        float4 v1 = *(const float4*)(p + tsub * 8 + 4);
        y0 += v0.x; y1v += v0.y; y2v += v0.z; y3 += v0.w;
        y4 += v1.x; y5 += v1.y; y6 += v1.z; y7 += v1.w;
        sp += p[32];
    }
    float inv = 1.f / sp;
    int cb = tsub * 8;
    s_y[q_local][cb + 0] = y0 * inv;  s_y[q_local][cb + 1] = y1v * inv;
    s_y[q_local][cb + 2] = y2v * inv; s_y[q_local][cb + 3] = y3 * inv;
    s_y[q_local][cb + 4] = y4 * inv;  s_y[q_local][cb + 5] = y5 * inv;
    s_y[q_local][cb + 6] = y6 * inv;  s_y[q_local][cb + 7] = y7 * inv;
    __syncthreads();

    float ya[16], yb[16];
    #pragma unroll
    for (int i = 0; i < 16; i++) { ya[i] = s_y[q_local][i]; yb[i] = s_y[q_local][16 + i]; }

    int n = q;
    #pragma unroll 1
    for (int cc = 0; cc < 16; cc++) {
        int c = tsub * 16 + cc;
        float d1 = 0.f, d2 = 0.f;
        #pragma unroll
        for (int i = 0; i < 16; i++) {
            float w = s_w[c * CI + i];
            d1 = fmaf(w, ya[i], d1);
            d2 = fmaf(w, yb[i], d2);
        }
        float sc = s_scale[c], bi = s_bias[c];
        out[((size_t)(b * 128) + c) * NN + n] =
            fmaf(sc, d1, bi) + x[((size_t)(b * Cc) + c) * NN + n];
        out[((size_t)(b * 128) + 64 + c) * NN + n] =
            fmaf(sc, d2, bi) + bfimg[((size_t)(b * Cc) + c) * NN + n];
    }
}

// ---------------------------------------------------------------------------
extern "C" void kernel_launch(void* const* d_in, const int* in_sizes, int n_in,
                              void* d_out, int out_size)
{
    const float* bfimg   = (const float*)d_in[0];
    const float* x       = (const float*)d_in[1];
    const float* w_theta = (const float*)d_in[2];
    const float* b_theta = (const float*)d_in[3];
    const float* w_phi   = (const float*)d_in[4];
    const float* b_phi   = (const float*)d_in[5];
    const float* w_g     = (const float*)d_in[6];
    const float* b_g     = (const float*)d_in[7];
    const float* w_gbf   = (const float*)d_in[8];
    const float* b_gbf   = (const float*)d_in[9];
    const float* w_W     = (const float*)d_in[10];
    const float* b_W     = (const float*)d_in[11];
    const float* bn_gamma= (const float*)d_in[12];
    const float* bn_beta = (const float*)d_in[13];
    const float* bn_mean = (const float*)d_in[14];
    const float* bn_var  = (const float*)d_in[15];
    float* out = (float*)d_out;

    proj_kernel<<<dim3((Bb * NN) / 128, 1, 4), 128>>>(bfimg, x, w_theta, b_theta,
                                                      w_phi, b_phi, w_g, b_g,
                                                      w_gbf, b_gbf);
    attn_kernel<<<dim3(NN / 64, Bb, KSPLIT), 128>>>();
    combine_kernel<<<dim3(NN / 64, Bb), 256>>>(bfimg, x, w_W, b_W,
                                               bn_gamma, bn_beta, bn_mean, bn_var, out);
}

// round 16
// speedup vs baseline: 1.5267x; 1.0149x over previous
#include <cuda_runtime.h>
#include <cuda_bf16.h>
#include <cstdint>

// ---------------------------------------------------------------------------
// NONLocalBlock2D: B=2, C=64, Ci=16, H=W=80, N=6400
// Round 14: HMMA flash attention, KSPLIT=10 (2000 CTAs, ~13.5/SM) +
// proj with full-MLP v[64] loads split by (tensor, channel-half) -> 8 z-slices.
// ---------------------------------------------------------------------------

#define Bb 2
#define Cc 64
#define CI 16
#define NN 6400
#define KSPLIT 10
#define LOG2E 1.4426950408889634f

#define PHI_PITCH 48     // bytes/row (12 floats): conflict-free
#define G_PITCH   304    // bytes/row (76 floats): 76 mod 32 = 12 -> conflict-free

__device__ __forceinline__ float ex2_approx(float v) {
    float r;
    asm("ex2.approx.f32 %0, %1;" : "=f"(r) : "f"(v));
    return r;
}
__device__ __forceinline__ uint32_t pack_bf16(float lo, float hi) {
    uint32_t r;
    asm("cvt.rn.bf16x2.f32 %0, %1, %2;" : "=r"(r) : "f"(hi), "f"(lo));
    return r;
}
__device__ __forceinline__ void mma16816(float c[4], const uint32_t a[4],
                                         uint32_t b0, uint32_t b1) {
    asm volatile(
        "mma.sync.aligned.m16n8k16.row.col.f32.bf16.bf16.f32 "
        "{%0,%1,%2,%3}, {%4,%5,%6,%7}, {%8,%9}, {%0,%1,%2,%3};"
        : "+f"(c[0]), "+f"(c[1]), "+f"(c[2]), "+f"(c[3])
        : "r"(a[0]), "r"(a[1]), "r"(a[2]), "r"(a[3]), "r"(b0), "r"(b1));
}

// Scratch (static device globals: no runtime allocation)
__device__ __align__(256) unsigned int   d_thetab[Bb * NN * 8];   // bf16x2, log2e folded
__device__ __align__(256) unsigned int   d_phib  [Bb * NN * 8];   // bf16x2
__device__ __align__(256) __nv_bfloat16  d_gvt   [Bb * 32 * NN];  // [b][ch][n]; 0:16 g_x, 16:32 g_bf
__device__ __align__(256) float          d_part  [KSPLIT * Bb * NN * 36];  // 18.4 MB

// ---------------------------------------------------------------------------
// Kernel 1: projections. gridDim.z = 8: z>>1 selects tensor
// (0:theta 1:phi 2:g_bf 3:g_x), z&1 selects output-channel half (8 ch).
// One thread per pixel; full v[64] burst (MLP=64); 8 accumulator chains.
// ---------------------------------------------------------------------------
__global__ __launch_bounds__(256) void proj_kernel(
    const float* __restrict__ bfimg, const float* __restrict__ x,
    const float* __restrict__ w_theta, const float* __restrict__ b_theta,
    const float* __restrict__ w_phi,   const float* __restrict__ b_phi,
    const float* __restrict__ w_g,     const float* __restrict__ b_g,
    const float* __restrict__ w_gbf,   const float* __restrict__ b_gbf)
{
    __shared__ float sw[8 * Cc];
    __shared__ float sb[8];

    int tid = threadIdx.x;
    int z = blockIdx.z;
    int ten = z >> 1;      // tensor
    int half = z & 1;      // output-channel half

    const float* W  = (ten == 0) ? w_theta : (ten == 1) ? w_phi : (ten == 2) ? w_gbf : w_g;
    const float* Bv = (ten == 0) ? b_theta : (ten == 1) ? b_phi : (ten == 2) ? b_gbf : b_g;
    const float* src = (ten == 3) ? x : bfimg;

    for (int i = tid; i < 8 * Cc; i += 256) sw[i] = W[half * 8 * Cc + i];
    if (tid < 8) sb[tid] = Bv[half * 8 + tid];
    __syncthreads();

    int pix = blockIdx.x * 256 + tid;          // 0 .. 12799
    int b = pix / NN;
    int n = pix - b * NN;

    const float* in = src + (size_t)(b * Cc) * NN + n;
    float v[Cc];
    #pragma unroll
    for (int c = 0; c < Cc; c++) v[c] = in[(size_t)c * NN];

    float outv[8];
    #pragma unroll
    for (int ci = 0; ci < 8; ci++) {
        const float* wr = &sw[ci * Cc];
        float a0 = sb[ci], a1 = 0.f, a2 = 0.f, a3 = 0.f;
        #pragma unroll
        for (int c = 0; c < Cc; c += 4) {
            a0 = fmaf(wr[c],     v[c],     a0);
            a1 = fmaf(wr[c + 1], v[c + 1], a1);
            a2 = fmaf(wr[c + 2], v[c + 2], a2);
            a3 = fmaf(wr[c + 3], v[c + 3], a3);
        }
        outv[ci] = (a0 + a1) + (a2 + a3);
    }

    if (ten <= 1) {
        float s = (ten == 0) ? LOG2E : 1.f;
        unsigned int pk[4];
        #pragma unroll
        for (int j = 0; j < 4; j++)
            pk[j] = pack_bf16(outv[2 * j] * s, outv[2 * j + 1] * s);
        unsigned int* dst = (ten == 0) ? d_thetab : d_phib;
        *(uint4*)&dst[(size_t)pix * 8 + half * 4] = make_uint4(pk[0], pk[1], pk[2], pk[3]);
    } else {
        int ch0 = ((ten == 2) ? 16 : 0) + half * 8;
        #pragma unroll
        for (int ci = 0; ci < 8; ci++)
            d_gvt[(size_t)(b * 32 + ch0 + ci) * NN + n] = __float2bfloat16(outv[ci]);
    }
}

// ---------------------------------------------------------------------------
// Kernel 2: HMMA flash attention. Grid (NN/64=100, Bb, KSPLIT=10) = 2000 CTAs,
// 128 threads = 4 warps x 16 queries. 5 tiles of 128 keys per split.
// ---------------------------------------------------------------------------
__global__ __launch_bounds__(128) void attn_kernel()
{
    __shared__ __align__(16) char s_phi[128 * PHI_PITCH];  // 6144 B
    __shared__ __align__(16) char s_g[32 * G_PITCH];       // 9728 B

    int tid = threadIdx.x;
    int wid = tid >> 5, lane = tid & 31;
    int g = lane >> 2, t = lane & 3;
    int b = blockIdx.y, split = blockIdx.z;
    int qbase = blockIdx.x * 64;
    int kstart = split * (NN / KSPLIT);        // 640 keys per split
    const int ntiles = (NN / KSPLIT) / 128;    // 5

    int q0 = qbase + wid * 16 + g;             // rows g and g+8 of this warp's M=16

    // theta A-fragment (constant for whole kernel)
    uint32_t a_th[4];
    {
        const unsigned int* th0 = d_thetab + ((size_t)b * NN + q0) * 8;
        const unsigned int* th1 = th0 + 8 * 8;       // q0 + 8
        a_th[0] = th0[t];     a_th[1] = th1[t];
        a_th[2] = th0[t + 4]; a_th[3] = th1[t + 4];
    }

    float o[4][4];
    #pragma unroll
    for (int nb = 0; nb < 4; nb++)
        #pragma unroll
        for (int i = 0; i < 4; i++) o[nb][i] = 0.f;
    float sumA = 0.f, sumB = 0.f;

    for (int tt = 0; tt < ntiles; tt++) {
        int kbase = kstart + tt * 128;
        __syncthreads();
        // phi tile: 128 keys x 32B -> rows of PHI_PITCH
        {
            const float4* src = (const float4*)(d_phib + ((size_t)b * NN + kbase) * 8);
            #pragma unroll
            for (int i = tid; i < 256; i += 128) {
                int key = i >> 1, h = i & 1;
                *(float4*)(s_phi + key * PHI_PITCH + h * 16) = src[i];
            }
        }
        // g tile: 32 ch x 128 keys (256B) -> rows of G_PITCH
        {
            #pragma unroll
            for (int i = tid; i < 512; i += 128) {
                int ch = i >> 4, seg = i & 15;
                const float4* src = (const float4*)(d_gvt + (size_t)(b * 32 + ch) * NN + kbase + seg * 8);
                *(float4*)(s_g + ch * G_PITCH + seg * 16) = src[0];
            }
        }
        __syncthreads();

        #pragma unroll 2
        for (int kk = 0; kk < 8; kk++) {
            // MMA1: two S tiles (keys 16kk .. 16kk+15)
            float s0[4] = {0.f, 0.f, 0.f, 0.f};
            float s1[4] = {0.f, 0.f, 0.f, 0.f};
            {
                const char* r0 = s_phi + (16 * kk + g) * PHI_PITCH + 4 * t;
                mma16816(s0, a_th, *(const uint32_t*)r0, *(const uint32_t*)(r0 + 16));
                const char* r1 = r0 + 8 * PHI_PITCH;
                mma16816(s1, a_th, *(const uint32_t*)r1, *(const uint32_t*)(r1 + 16));
            }
            // exp (ex2; theta pre-scaled by log2e)
            #pragma unroll
            for (int i = 0; i < 4; i++) {
                s0[i] = ex2_approx(s0[i]);
                s1[i] = ex2_approx(s1[i]);
            }
            sumA += (s0[0] + s0[1]) + (s1[0] + s1[1]);
            sumB += (s0[2] + s0[3]) + (s1[2] + s1[3]);
            // C-frag -> A-frag repack (P, K=16 keys)
            uint32_t a_p[4];
            a_p[0] = pack_bf16(s0[0], s0[1]);
            a_p[1] = pack_bf16(s0[2], s0[3]);
            a_p[2] = pack_bf16(s1[0], s1[1]);
            a_p[3] = pack_bf16(s1[2], s1[3]);
            // MMA2: O += P @ g^T over 4 channel blocks
            const char* gb = s_g + g * G_PITCH + 32 * kk + 4 * t;
            #pragma unroll
            for (int nb = 0; nb < 4; nb++) {
                const char* r = gb + nb * 8 * G_PITCH;
                mma16816(o[nb], a_p, *(const uint32_t*)r, *(const uint32_t*)(r + 16));
            }
        }
    }

    // row sums: reduce over the quad (t)
    sumA += __shfl_xor_sync(0xFFFFFFFFu, sumA, 1);
    sumA += __shfl_xor_sync(0xFFFFFFFFu, sumA, 2);
    sumB += __shfl_xor_sync(0xFFFFFFFFu, sumB, 1);
    sumB += __shfl_xor_sync(0xFFFFFFFFu, sumB, 2);

    // write unnormalized partials
    {
        size_t base0 = (((size_t)split * Bb + b) * NN + q0) * 36;
        size_t base1 = base0 + 8 * 36;       // q0 + 8
        #pragma unroll
        for (int nb = 0; nb < 4; nb++) {
            int ch = 8 * nb + 2 * t;
            *(float2*)(d_part + base0 + ch) = make_float2(o[nb][0], o[nb][1]);
            *(float2*)(d_part + base1 + ch) = make_float2(o[nb][2], o[nb][3]);
        }
        if (t == 0) {
            d_part[base0 + 32] = sumA;
            d_part[base1 + 32] = sumB;
        }
    }
}

// ---------------------------------------------------------------------------
// Kernel 3: combine splits, normalize, W/BN/residual epilogue. fp32.
// ---------------------------------------------------------------------------
__global__ __launch_bounds__(256) void combine_kernel(
    const float* __restrict__ bfimg, const float* __restrict__ x,
    const float* __restrict__ w_W,   const float* __restrict__ b_W,
    const float* __restrict__ bn_gamma, const float* __restrict__ bn_beta,
    const float* __restrict__ bn_mean,  const float* __restrict__ bn_var,
    float* __restrict__ out)
{
    __shared__ float s_w[Cc * CI];
    __shared__ float s_scale[Cc];
    __shared__ float s_bias[Cc];
    __shared__ float s_y[64][36];

    int tid = threadIdx.x;
    int b = blockIdx.y;
    int q_local = tid >> 2;
    int tsub = tid & 3;
    int q = blockIdx.x * 64 + q_local;

    for (int i = tid; i < Cc * CI; i += 256) s_w[i] = w_W[i];
    if (tid < Cc) {
        float sc = bn_gamma[tid] * rsqrtf(bn_var[tid] + 1e-5f);
        s_scale[tid] = sc;
        s_bias[tid] = (b_W[tid] - bn_mean[tid]) * sc + bn_beta[tid];
    }

    float y0 = 0.f, y1v = 0.f, y2v = 0.f, y3 = 0.f, y4 = 0.f, y5 = 0.f, y6 = 0.f, y7 = 0.f;
    float sp = 0.f;
    #pragma unroll
    for (int s = 0; s < KSPLIT; s++) {
        const float* p = d_part + (((size_t)s * Bb + b) * NN + q) * 36;
        float4 v0 = *(const float4*)(p + tsub * 8);
        float4 v1 = *(const float4*)(p + tsub * 8 + 4);
        y0 += v0.x; y1v += v0.y; y2v += v0.z; y3 += v0.w;
        y4 += v1.x; y5 += v1.y; y6 += v1.z; y7 += v1.w;
        sp += p[32];
    }
    float inv = 1.f / sp;
    int cb = tsub * 8;
    s_y[q_local][cb + 0] = y0 * inv;  s_y[q_local][cb + 1] = y1v * inv;
    s_y[q_local][cb + 2] = y2v * inv; s_y[q_local][cb + 3] = y3 * inv;
    s_y[q_local][cb + 4] = y4 * inv;  s_y[q_local][cb + 5] = y5 * inv;
    s_y[q_local][cb + 6] = y6 * inv;  s_y[q_local][cb + 7] = y7 * inv;
    __syncthreads();

    float ya[16], yb[16];
    #pragma unroll
    for (int i = 0; i < 16; i++) { ya[i] = s_y[q_local][i]; yb[i] = s_y[q_local][16 + i]; }

    int n = q;
    #pragma unroll 1
    for (int cc = 0; cc < 16; cc++) {
        int c = tsub * 16 + cc;
        float d1 = 0.f, d2 = 0.f;
        #pragma unroll
        for (int i = 0; i < 16; i++) {
            float w = s_w[c * CI + i];
            d1 = fmaf(w, ya[i], d1);
            d2 = fmaf(w, yb[i], d2);
        }
        float sc = s_scale[c], bi = s_bias[c];
        out[((size_t)(b * 128) + c) * NN + n] =
            fmaf(sc, d1, bi) + x[((size_t)(b * Cc) + c) * NN + n];
        out[((size_t)(b * 128) + 64 + c) * NN + n] =
            fmaf(sc, d2, bi) + bfimg[((size_t)(b * Cc) + c) * NN + n];
    }
}

// ---------------------------------------------------------------------------
extern "C" void kernel_launch(void* const* d_in, const int* in_sizes, int n_in,
                              void* d_out, int out_size)
{
    const float* bfimg   = (const float*)d_in[0];
    const float* x       = (const float*)d_in[1];
    const float* w_theta = (const float*)d_in[2];
    const float* b_theta = (const float*)d_in[3];
    const float* w_phi   = (const float*)d_in[4];
    const float* b_phi   = (const float*)d_in[5];
    const float* w_g     = (const float*)d_in[6];
    const float* b_g     = (const float*)d_in[7];
    const float* w_gbf   = (const float*)d_in[8];
    const float* b_gbf   = (const float*)d_in[9];
    const float* w_W     = (const float*)d_in[10];
    const float* b_W     = (const float*)d_in[11];
    const float* bn_gamma= (const float*)d_in[12];
    const float* bn_beta = (const float*)d_in[13];
    const float* bn_mean = (const float*)d_in[14];
    const float* bn_var  = (const float*)d_in[15];
    float* out = (float*)d_out;

    proj_kernel<<<dim3((Bb * NN) / 256, 1, 8), 256>>>(bfimg, x, w_theta, b_theta,
                                                      w_phi, b_phi, w_g, b_g,
                                                      w_gbf, b_gbf);
    attn_kernel<<<dim3(NN / 64, Bb, KSPLIT), 128>>>();
    combine_kernel<<<dim3(NN / 64, Bb), 256>>>(bfimg, x, w_W, b_W,
                                               bn_gamma, bn_beta, bn_mean, bn_var, out);
}